// round 16
// baseline (speedup 1.0000x reference)
#include <cuda_runtime.h>
#include <cuda_fp16.h>
#include <cstdint>

// NeuralNetwork_28819230556388 — B=262144, D=64, 13 chained 64x64 GEMMs.
// R16: R15 (fp16 single-product, 2 groups/warp, 3 slots/group, interleaved
// next+skip, half2 epilogue) + np-level SOFTWARE PIPELINE: B-fragments and
// bias for np+1 are double-buffered and prefetched during np's MMA/epilogue
// window, so MMA bursts never wait on LDSM (only one exposed LDSM per layer
// prologue instead of per np). Arithmetic bit-identical (rel_err 4.0948e-4).
// Bias-in-accumulator, weights SMEM-resident, persistent CTAs, no barriers.

#define TPB     256
#define GRID    148
#define NMAC    8192                  // 262144 / 32 rows per macro-group
#define WSTEP   (GRID * (TPB / 32))   // 1184 warps

// SMEM layout (bytes)
#define OFF_BN 0                      // 7*64 f32 = 1792
#define OFF_BS 1792                   // 6*64 f32 = 1536
#define OFF_W  4096                   // 13 mats * 8192 fp16
#define SMEM_TOTAL (4096 + 13*8192)   // 110592

#define SMEM_SWIZZLE_128B(bo) ((bo) ^ (((bo) >> 3) & 0x70))

__device__ __forceinline__ uint32_t smem_to_u32(const void* p) {
    uint32_t a;
    asm("{ .reg .u64 t; cvta.to.shared.u64 t, %1; cvt.u32.u64 %0, t; }"
        : "=r"(a) : "l"(p));
    return a;
}

#define LDSM_X4(r, addr) \
    asm volatile("ldmatrix.sync.aligned.m8n8.x4.shared.b16 {%0,%1,%2,%3}, [%4];" \
        : "=r"((r)[0]), "=r"((r)[1]), "=r"((r)[2]), "=r"((r)[3]) \
        : "r"(addr))

__device__ __forceinline__ void mma_f16(float d[4], const uint32_t a[4],
                                        uint32_t b0, uint32_t b1) {
    asm volatile(
        "mma.sync.aligned.m16n8k16.row.col.f32.f16.f16.f32 "
        "{%0,%1,%2,%3}, {%4,%5,%6,%7}, {%8,%9}, {%0,%1,%2,%3};"
        : "+f"(d[0]), "+f"(d[1]), "+f"(d[2]), "+f"(d[3])
        : "r"(a[0]), "r"(a[1]), "r"(a[2]), "r"(a[3]), "r"(b0), "r"(b1));
}

__device__ __forceinline__ uint32_t pk_h2(float a, float b) {
    __half2 h = __floats2half2_rn(a, b);
    return *reinterpret_cast<uint32_t*>(&h);
}

// 16 rows x 64 cols activation fragment, fp16 A-frags [ktile][reg]
struct Frag {
    uint32_t a[4][4];
};

// half2 epilogue for one group's np: An = hmax2(dn,0) [+ hmax2(ds,0)]
template <bool HAS_SKIP>
__device__ __forceinline__ void epi_h2(const float dn[2][4], const float ds[2][4],
                                       Frag& An, int np)
{
    const __half2 z = __float2half2_rn(0.0f);
#pragma unroll
    for (int i2 = 0; i2 < 2; ++i2) {
        __half2 n01 = __floats2half2_rn(dn[i2][0], dn[i2][1]);
        __half2 n23 = __floats2half2_rn(dn[i2][2], dn[i2][3]);
        n01 = __hmax2(n01, z);
        n23 = __hmax2(n23, z);
        if (HAS_SKIP) {
            __half2 s01 = __floats2half2_rn(ds[i2][0], ds[i2][1]);
            __half2 s23 = __floats2half2_rn(ds[i2][2], ds[i2][3]);
            n01 = __hadd2(n01, __hmax2(s01, z));
            n23 = __hadd2(n23, __hmax2(s23, z));
        }
        An.a[np][2 * i2]     = *reinterpret_cast<uint32_t*>(&n01);
        An.a[np][2 * i2 + 1] = *reinterpret_cast<uint32_t*>(&n23);
    }
}

// exact fp32 epilogue for the final layer (writes gmem)
template <bool HAS_SKIP>
__device__ __forceinline__ void epi_last(const float dn[2][4], const float ds[2][4],
                                         int np, int qt,
                                         float* __restrict__ out0,
                                         float* __restrict__ out1)
{
#pragma unroll
    for (int i2 = 0; i2 < 2; ++i2) {
        const int nt = 2 * np + i2;
        float v0 = fmaxf(dn[i2][0], 0.0f);
        float v1 = fmaxf(dn[i2][1], 0.0f);
        float v2 = fmaxf(dn[i2][2], 0.0f);
        float v3 = fmaxf(dn[i2][3], 0.0f);
        if (HAS_SKIP) {
            v0 += fmaxf(ds[i2][0], 0.0f);
            v1 += fmaxf(ds[i2][1], 0.0f);
            v2 += fmaxf(ds[i2][2], 0.0f);
            v3 += fmaxf(ds[i2][3], 0.0f);
        }
        *reinterpret_cast<float2*>(out0 + 8 * nt + 2 * qt) = make_float2(v0, v1);
        *reinterpret_cast<float2*>(out1 + 8 * nt + 2 * qt) = make_float2(v2, v3);
    }
}

// One layer, both groups, np-level software pipeline with B/bias double buffer.
// Ap* = h_{t-1}, As* = h_{t-2} (skip), An* = output slot (holds dead h_{t-3}).
template <bool HAS_SKIP, bool LAST>
__device__ __forceinline__ void layer_step(
    const Frag& Ap0, const Frag& As0, Frag& An0,
    const Frag& Ap1, const Frag& As1, Frag& An1,
    uint32_t wn, uint32_t ws,
    const float* __restrict__ bnp, const float* __restrict__ bsp,
    uint32_t soff0, uint32_t soff1, int qt,
    float* __restrict__ o00, float* __restrict__ o01,
    float* __restrict__ o10, float* __restrict__ o11)
{
    uint32_t Bn[2][2][8], Bs[2][2][8];   // [buf][i2][reg]
    float bb[2][2], sb[2][2];            // bias staging for the CURRENT np

    // ---- prologue: B + bias for np = 0 into buffer 0 ----
#pragma unroll
    for (int i2 = 0; i2 < 2; ++i2) {
        uint32_t a = wn + (uint32_t)i2 * 1024;
        LDSM_X4(&Bn[0][i2][0], a + soff0);
        LDSM_X4(&Bn[0][i2][4], a + soff1);
        if (HAS_SKIP) {
            uint32_t s = ws + (uint32_t)i2 * 1024;
            LDSM_X4(&Bs[0][i2][0], s + soff0);
            LDSM_X4(&Bs[0][i2][4], s + soff1);
        }
        float2 b2 = *reinterpret_cast<const float2*>(bnp + 8 * i2 + 2 * qt);
        bb[i2][0] = b2.x; bb[i2][1] = b2.y;
        if (HAS_SKIP) {
            float2 s2 = *reinterpret_cast<const float2*>(bsp + 8 * i2 + 2 * qt);
            sb[i2][0] = s2.x; sb[i2][1] = s2.y;
        }
    }

    float dn0[2][4], dn1[2][4], ds0[2][4], ds1[2][4];

#pragma unroll
    for (int np = 0; np < 4; ++np) {
        const int cur = np & 1, nxt = cur ^ 1;

        // ---- bias-init accumulators (bias staged last iteration) ----
#pragma unroll
        for (int i2 = 0; i2 < 2; ++i2) {
            dn0[i2][0] = bb[i2][0]; dn0[i2][1] = bb[i2][1];
            dn0[i2][2] = bb[i2][0]; dn0[i2][3] = bb[i2][1];
            dn1[i2][0] = bb[i2][0]; dn1[i2][1] = bb[i2][1];
            dn1[i2][2] = bb[i2][0]; dn1[i2][3] = bb[i2][1];
            if (HAS_SKIP) {
                ds0[i2][0] = sb[i2][0]; ds0[i2][1] = sb[i2][1];
                ds0[i2][2] = sb[i2][0]; ds0[i2][3] = sb[i2][1];
                ds1[i2][0] = sb[i2][0]; ds1[i2][1] = sb[i2][1];
                ds1[i2][2] = sb[i2][0]; ds1[i2][3] = sb[i2][1];
            }
        }

        // ---- MMA stream: 8 independent chains, B already resident ----
#pragma unroll
        for (int kt = 0; kt < 4; ++kt)
#pragma unroll
            for (int i2 = 0; i2 < 2; ++i2) {
                mma_f16(dn0[i2], Ap0.a[kt], Bn[cur][i2][2 * kt], Bn[cur][i2][2 * kt + 1]);
                mma_f16(dn1[i2], Ap1.a[kt], Bn[cur][i2][2 * kt], Bn[cur][i2][2 * kt + 1]);
                if (HAS_SKIP) {
                    mma_f16(ds0[i2], As0.a[kt], Bs[cur][i2][2 * kt], Bs[cur][i2][2 * kt + 1]);
                    mma_f16(ds1[i2], As1.a[kt], Bs[cur][i2][2 * kt], Bs[cur][i2][2 * kt + 1]);
                }
            }

        // ---- prefetch np+1's B + bias while MMAs drain ----
        if (np < 3) {
#pragma unroll
            for (int i2 = 0; i2 < 2; ++i2) {
                uint32_t a = wn + (uint32_t)(2 * (np + 1) + i2) * 1024;
                LDSM_X4(&Bn[nxt][i2][0], a + soff0);
                LDSM_X4(&Bn[nxt][i2][4], a + soff1);
                if (HAS_SKIP) {
                    uint32_t s = ws + (uint32_t)(2 * (np + 1) + i2) * 1024;
                    LDSM_X4(&Bs[nxt][i2][0], s + soff0);
                    LDSM_X4(&Bs[nxt][i2][4], s + soff1);
                }
                float2 b2 = *reinterpret_cast<const float2*>(bnp + 8 * (2 * (np + 1) + i2) + 2 * qt);
                bb[i2][0] = b2.x; bb[i2][1] = b2.y;
                if (HAS_SKIP) {
                    float2 s2 = *reinterpret_cast<const float2*>(bsp + 8 * (2 * (np + 1) + i2) + 2 * qt);
                    sb[i2][0] = s2.x; sb[i2][1] = s2.y;
                }
            }
        }

        // ---- epilogue(np): runs while prefetch LDSMs are in flight ----
        if (LAST) {
            epi_last<HAS_SKIP>(dn0, ds0, np, qt, o00, o01);
            epi_last<HAS_SKIP>(dn1, ds1, np, qt, o10, o11);
        } else {
            epi_h2<HAS_SKIP>(dn0, ds0, An0, np);
            epi_h2<HAS_SKIP>(dn1, ds1, An1, np);
        }
    }
}

// load 16 rows of x into a Frag (fp16)
__device__ __forceinline__ void load_x(const float* __restrict__ xr0,
                                       const float* __restrict__ xr1,
                                       Frag& A, int qt)
{
#pragma unroll
    for (int kt = 0; kt < 4; ++kt) {
        const int c = 16 * kt + 2 * qt;
        float2 p0 = *reinterpret_cast<const float2*>(xr0 + c);
        float2 p1 = *reinterpret_cast<const float2*>(xr1 + c);
        float2 p2 = *reinterpret_cast<const float2*>(xr0 + c + 8);
        float2 p3 = *reinterpret_cast<const float2*>(xr1 + c + 8);
        A.a[kt][0] = pk_h2(p0.x, p0.y);
        A.a[kt][1] = pk_h2(p1.x, p1.y);
        A.a[kt][2] = pk_h2(p2.x, p2.y);
        A.a[kt][3] = pk_h2(p3.x, p3.y);
    }
}

__global__ void __launch_bounds__(TPB, 1)
nn_mma_kernel(const float* __restrict__ x,
              const float* __restrict__ Wn_g,
              const float* __restrict__ bn_g,
              const float* __restrict__ Ws_g,
              const float* __restrict__ bs_g,
              float* __restrict__ out)
{
    extern __shared__ unsigned char sm[];
    const uint32_t smb = smem_to_u32(sm);
    const int tid  = threadIdx.x;
    const int wid  = tid >> 5;
    const int lane = tid & 31;
    const int qt   = lane & 3;
    const int grp  = lane >> 2;

    // ---- stage 13 weight matrices as fp16, [n][k] row-major, SW128 ----
    for (int idx = tid; idx < 13 * 4096; idx += TPB) {
        int mat = idx >> 12, e = idx & 4095;
        float v = (mat < 7) ? Wn_g[mat * 4096 + e] : Ws_g[(mat - 7) * 4096 + e];
        int n = e >> 6, k = e & 63;
        uint32_t sw = SMEM_SWIZZLE_128B((uint32_t)(n * 128 + k * 2));
        *reinterpret_cast<__half*>(sm + OFF_W + mat * 8192 + sw) = __float2half_rn(v);
    }
    for (int i = tid; i < 448; i += TPB)
        reinterpret_cast<float*>(sm + OFF_BN)[i] = bn_g[i];
    for (int i = tid; i < 384; i += TPB)
        reinterpret_cast<float*>(sm + OFF_BS)[i] = bs_g[i];
    __syncthreads();

    // per-thread ldmatrix.x4 swizzled offsets (k halves 0-31 / 32-63)
    const int r8 = lane & 7, b4 = lane >> 3;
    const uint32_t soff0 = (uint32_t)(r8 * 128 + ((b4 * 16)      ^ (r8 * 16)));
    const uint32_t soff1 = (uint32_t)(r8 * 128 + ((b4 * 16 + 64) ^ (r8 * 16)));

    const float* bn = reinterpret_cast<const float*>(sm + OFF_BN);
    const float* bs = reinterpret_cast<const float*>(sm + OFF_BS);
    const uint32_t w0 = smb + OFF_W;

    // warps independent: global warp-strided loop over 32-row macro-groups
    const int gw = blockIdx.x * (TPB / 32) + wid;

    for (int g = gw; g < NMAC; g += WSTEP) {
        const size_t r00 = (size_t)g * 32 + grp;       // group0 rows
        const size_t r01 = r00 + 8;
        const size_t r10 = r00 + 16;                   // group1 rows
        const size_t r11 = r00 + 24;

        // 3 slots per group: h_t lives in S[t % 3] (S0 starts as h0 = x)
        Frag S0g0, S1g0, S2g0, S0g1, S1g1, S2g1;
        load_x(x + r00 * 64, x + r01 * 64, S0g0, qt);
        load_x(x + r10 * 64, x + r11 * 64, S0g1, qt);

        float* o00 = out + r00 * 64;
        float* o01 = out + r01 * 64;
        float* o10 = out + r10 * 64;
        float* o11 = out + r11 * 64;

        // layer t: Ap = S[(t-1)%3], As = S[(t-2)%3], An = S[t%3] (dead h_{t-3})
        layer_step<false, false>(S0g0, S0g0, S1g0, S0g1, S0g1, S1g1,
                                 w0 + 0 * 8192, 0, bn + 0 * 64, bs,
                                 soff0, soff1, qt, o00, o01, o10, o11);          // h1->S1
        layer_step<true,  false>(S1g0, S0g0, S2g0, S1g1, S0g1, S2g1,
                                 w0 + 1 * 8192, w0 + 7 * 8192,
                                 bn + 1 * 64, bs + 0 * 64,
                                 soff0, soff1, qt, o00, o01, o10, o11);          // h2->S2
        layer_step<true,  false>(S2g0, S1g0, S0g0, S2g1, S1g1, S0g1,
                                 w0 + 2 * 8192, w0 + 8 * 8192,
                                 bn + 2 * 64, bs + 1 * 64,
                                 soff0, soff1, qt, o00, o01, o10, o11);          // h3->S0
        layer_step<true,  false>(S0g0, S2g0, S1g0, S0g1, S2g1, S1g1,
                                 w0 + 3 * 8192, w0 + 9 * 8192,
                                 bn + 3 * 64, bs + 2 * 64,
                                 soff0, soff1, qt, o00, o01, o10, o11);          // h4->S1
        layer_step<true,  false>(S1g0, S0g0, S2g0, S1g1, S0g1, S2g1,
                                 w0 + 4 * 8192, w0 + 10 * 8192,
                                 bn + 4 * 64, bs + 3 * 64,
                                 soff0, soff1, qt, o00, o01, o10, o11);          // h5->S2
        layer_step<true,  false>(S2g0, S1g0, S0g0, S2g1, S1g1, S0g1,
                                 w0 + 5 * 8192, w0 + 11 * 8192,
                                 bn + 5 * 64, bs + 4 * 64,
                                 soff0, soff1, qt, o00, o01, o10, o11);          // h6->S0
        layer_step<true,  true >(S0g0, S2g0, S1g0, S0g1, S2g1, S1g1,
                                 w0 + 6 * 8192, w0 + 12 * 8192,
                                 bn + 6 * 64, bs + 5 * 64,
                                 soff0, soff1, qt, o00, o01, o10, o11);          // h7->out
    }
}

extern "C" void kernel_launch(void* const* d_in, const int* in_sizes, int n_in,
                              void* d_out, int out_size)
{
    const float* x  = (const float*)d_in[0];
    const float* Wn = (const float*)d_in[1];
    const float* bn = (const float*)d_in[2];
    const float* Ws = (const float*)d_in[3];
    const float* bs = (const float*)d_in[4];
    float* out = (float*)d_out;

    cudaFuncSetAttribute(nn_mma_kernel,
                         cudaFuncAttributeMaxDynamicSharedMemorySize, SMEM_TOTAL);
    nn_mma_kernel<<<GRID, TPB, SMEM_TOTAL>>>(x, Wn, bn, Ws, bs, out);
}

// round 17
// speedup vs baseline: 1.0029x; 1.0029x over previous
#include <cuda_runtime.h>
#include <cuda_fp16.h>
#include <cstdint>

// NeuralNetwork_28819230556388 — B=262144, D=64, 13 chained 64x64 GEMMs.
// R17: R15 base (fp16 single-product, 2 groups/warp, 3 slots/group,
// interleaved next+skip MMA streams; R16's pipeline reverted — it regressed).
// New instruction-count cuts:
//  (a) zero-C first MMA: chains start as D = A*B + Zquad (separate C operand)
//      — deletes 32 accumulator-init MOVs per np (128 per layer-group).
//  (b) bias folded into the half2 epilogue as pre-packed half2 from SMEM:
//      n = hmax2(hadd2(pack(d), bh), 0). One extra fp16 rounding per branch
//      (predicted rel_err ~5e-4, margin ~2x). LAST layer keeps exact fp32
//      epilogue with fp32 bias.
// Weights SMEM-resident, persistent CTAs, no barriers in the main loop.

#define TPB     256
#define GRID    148
#define NMAC    8192                  // 262144 / 32 rows per macro-group
#define WSTEP   (GRID * (TPB / 32))   // 1184 warps

// SMEM layout (bytes)
#define OFF_BN  0                     // 7*64 f32 = 1792 (fp32, LAST layer)
#define OFF_BS  1792                  // 6*64 f32 = 1536
#define OFF_BNH 3328                  // 7*32 half2 = 896
#define OFF_BSH 4224                  // 6*32 half2 = 768
#define OFF_W   5120                  // 13 mats * 8192 fp16
#define SMEM_TOTAL (5120 + 13*8192)   // 111616

#define SMEM_SWIZZLE_128B(bo) ((bo) ^ (((bo) >> 3) & 0x70))

__device__ __forceinline__ uint32_t smem_to_u32(const void* p) {
    uint32_t a;
    asm("{ .reg .u64 t; cvta.to.shared.u64 t, %1; cvt.u32.u64 %0, t; }"
        : "=r"(a) : "l"(p));
    return a;
}

#define LDSM_X4(r, addr) \
    asm volatile("ldmatrix.sync.aligned.m8n8.x4.shared.b16 {%0,%1,%2,%3}, [%4];" \
        : "=r"((r)[0]), "=r"((r)[1]), "=r"((r)[2]), "=r"((r)[3]) \
        : "r"(addr))

// accumulate form: d += a*b
__device__ __forceinline__ void mma_f16(float d[4], const uint32_t a[4],
                                        uint32_t b0, uint32_t b1) {
    asm volatile(
        "mma.sync.aligned.m16n8k16.row.col.f32.f16.f16.f32 "
        "{%0,%1,%2,%3}, {%4,%5,%6,%7}, {%8,%9}, {%0,%1,%2,%3};"
        : "+f"(d[0]), "+f"(d[1]), "+f"(d[2]), "+f"(d[3])
        : "r"(a[0]), "r"(a[1]), "r"(a[2]), "r"(a[3]), "r"(b0), "r"(b1));
}

// chain-start form: d = a*b + z (z = pinned zero quad; no accumulator init)
__device__ __forceinline__ void mma_f16_zc(float d[4], const uint32_t a[4],
                                           uint32_t b0, uint32_t b1,
                                           const float z[4]) {
    asm volatile(
        "mma.sync.aligned.m16n8k16.row.col.f32.f16.f16.f32 "
        "{%0,%1,%2,%3}, {%4,%5,%6,%7}, {%8,%9}, {%10,%11,%12,%13};"
        : "=f"(d[0]), "=f"(d[1]), "=f"(d[2]), "=f"(d[3])
        : "r"(a[0]), "r"(a[1]), "r"(a[2]), "r"(a[3]), "r"(b0), "r"(b1),
          "f"(z[0]), "f"(z[1]), "f"(z[2]), "f"(z[3]));
}

__device__ __forceinline__ uint32_t pk_h2(float a, float b) {
    __half2 h = __floats2half2_rn(a, b);
    return *reinterpret_cast<uint32_t*>(&h);
}

// 16 rows x 64 cols activation fragment, fp16 A-frags [ktile][reg]
struct Frag {
    uint32_t a[4][4];
};

// half2 epilogue with bias: An = hmax2(pack(dn)+bh, 0) [+ hmax2(pack(ds)+sh, 0)]
template <bool HAS_SKIP>
__device__ __forceinline__ void epi_h2b(const float dn[2][4], const float ds[2][4],
                                        Frag& An, int np,
                                        const __half2* __restrict__ bnh,
                                        const __half2* __restrict__ bsh, int qt)
{
    const __half2 zz = __float2half2_rn(0.0f);
#pragma unroll
    for (int i2 = 0; i2 < 2; ++i2) {
        __half2 bh = bnh[(2 * np + i2) * 4 + qt];          // broadcast LDS.32
        __half2 n01 = __hmax2(__hadd2(__floats2half2_rn(dn[i2][0], dn[i2][1]), bh), zz);
        __half2 n23 = __hmax2(__hadd2(__floats2half2_rn(dn[i2][2], dn[i2][3]), bh), zz);
        if (HAS_SKIP) {
            __half2 sh = bsh[(2 * np + i2) * 4 + qt];
            n01 = __hadd2(n01, __hmax2(__hadd2(__floats2half2_rn(ds[i2][0], ds[i2][1]), sh), zz));
            n23 = __hadd2(n23, __hmax2(__hadd2(__floats2half2_rn(ds[i2][2], ds[i2][3]), sh), zz));
        }
        An.a[np][2 * i2]     = *reinterpret_cast<uint32_t*>(&n01);
        An.a[np][2 * i2 + 1] = *reinterpret_cast<uint32_t*>(&n23);
    }
}

// exact fp32 epilogue for the final layer (fp32 bias, writes gmem)
template <bool HAS_SKIP>
__device__ __forceinline__ void epi_last(const float dn[2][4], const float ds[2][4],
                                         int np, int qt,
                                         const float* __restrict__ bnp,
                                         const float* __restrict__ bsp,
                                         float* __restrict__ out0,
                                         float* __restrict__ out1)
{
#pragma unroll
    for (int i2 = 0; i2 < 2; ++i2) {
        const int nt = 2 * np + i2;
        float b0 = bnp[8 * nt + 2 * qt];
        float b1 = bnp[8 * nt + 2 * qt + 1];
        float v0 = fmaxf(dn[i2][0] + b0, 0.0f);
        float v1 = fmaxf(dn[i2][1] + b1, 0.0f);
        float v2 = fmaxf(dn[i2][2] + b0, 0.0f);
        float v3 = fmaxf(dn[i2][3] + b1, 0.0f);
        if (HAS_SKIP) {
            float s0 = bsp[8 * nt + 2 * qt];
            float s1 = bsp[8 * nt + 2 * qt + 1];
            v0 += fmaxf(ds[i2][0] + s0, 0.0f);
            v1 += fmaxf(ds[i2][1] + s1, 0.0f);
            v2 += fmaxf(ds[i2][2] + s0, 0.0f);
            v3 += fmaxf(ds[i2][3] + s1, 0.0f);
        }
        *reinterpret_cast<float2*>(out0 + 8 * nt + 2 * qt) = make_float2(v0, v1);
        *reinterpret_cast<float2*>(out1 + 8 * nt + 2 * qt) = make_float2(v2, v3);
    }
}

// One layer, both groups, fused per n-tile, next+skip interleaved, zero-C start.
// Ap* = h_{t-1}, As* = h_{t-2} (skip), An* = output slot (holds dead h_{t-3}).
template <bool HAS_SKIP, bool LAST>
__device__ __forceinline__ void layer_step(
    const Frag& Ap0, const Frag& As0, Frag& An0,
    const Frag& Ap1, const Frag& As1, Frag& An1,
    uint32_t wn, uint32_t ws,
    const __half2* __restrict__ bnh, const __half2* __restrict__ bsh,
    const float* __restrict__ bnp, const float* __restrict__ bsp,
    const float z[4],
    uint32_t soff0, uint32_t soff1, int qt,
    float* __restrict__ o00, float* __restrict__ o01,
    float* __restrict__ o10, float* __restrict__ o11)
{
#pragma unroll
    for (int np = 0; np < 4; ++np) {
        uint32_t Bn[2][8], Bs[2][8];
        float dn0[2][4], dn1[2][4], ds0[2][4], ds1[2][4];

        // ---- load BOTH weight fragment sets up front ----
#pragma unroll
        for (int i2 = 0; i2 < 2; ++i2) {
            uint32_t a = wn + (uint32_t)(2 * np + i2) * 1024;
            LDSM_X4(&Bn[i2][0], a + soff0);
            LDSM_X4(&Bn[i2][4], a + soff1);
        }
        if (HAS_SKIP) {
#pragma unroll
            for (int i2 = 0; i2 < 2; ++i2) {
                uint32_t s = ws + (uint32_t)(2 * np + i2) * 1024;
                LDSM_X4(&Bs[i2][0], s + soff0);
                LDSM_X4(&Bs[i2][4], s + soff1);
            }
        }

        // ---- interleaved MMA stream: 8 chains, kt=0 starts from zero-quad ----
#pragma unroll
        for (int kt = 0; kt < 4; ++kt)
#pragma unroll
            for (int i2 = 0; i2 < 2; ++i2) {
                if (kt == 0) {
                    mma_f16_zc(dn0[i2], Ap0.a[0], Bn[i2][0], Bn[i2][1], z);
                    mma_f16_zc(dn1[i2], Ap1.a[0], Bn[i2][0], Bn[i2][1], z);
                    if (HAS_SKIP) {
                        mma_f16_zc(ds0[i2], As0.a[0], Bs[i2][0], Bs[i2][1], z);
                        mma_f16_zc(ds1[i2], As1.a[0], Bs[i2][0], Bs[i2][1], z);
                    }
                } else {
                    mma_f16(dn0[i2], Ap0.a[kt], Bn[i2][2 * kt], Bn[i2][2 * kt + 1]);
                    mma_f16(dn1[i2], Ap1.a[kt], Bn[i2][2 * kt], Bn[i2][2 * kt + 1]);
                    if (HAS_SKIP) {
                        mma_f16(ds0[i2], As0.a[kt], Bs[i2][2 * kt], Bs[i2][2 * kt + 1]);
                        mma_f16(ds1[i2], As1.a[kt], Bs[i2][2 * kt], Bs[i2][2 * kt + 1]);
                    }
                }
            }

        // ---- inline epilogue ----
        if (LAST) {
            epi_last<HAS_SKIP>(dn0, ds0, np, qt, bnp, bsp, o00, o01);
            epi_last<HAS_SKIP>(dn1, ds1, np, qt, bnp, bsp, o10, o11);
        } else {
            epi_h2b<HAS_SKIP>(dn0, ds0, An0, np, bnh, bsh, qt);
            epi_h2b<HAS_SKIP>(dn1, ds1, An1, np, bnh, bsh, qt);
        }
    }
}

// load 16 rows of x into a Frag (fp16)
__device__ __forceinline__ void load_x(const float* __restrict__ xr0,
                                       const float* __restrict__ xr1,
                                       Frag& A, int qt)
{
#pragma unroll
    for (int kt = 0; kt < 4; ++kt) {
        const int c = 16 * kt + 2 * qt;
        float2 p0 = *reinterpret_cast<const float2*>(xr0 + c);
        float2 p1 = *reinterpret_cast<const float2*>(xr1 + c);
        float2 p2 = *reinterpret_cast<const float2*>(xr0 + c + 8);
        float2 p3 = *reinterpret_cast<const float2*>(xr1 + c + 8);
        A.a[kt][0] = pk_h2(p0.x, p0.y);
        A.a[kt][1] = pk_h2(p1.x, p1.y);
        A.a[kt][2] = pk_h2(p2.x, p2.y);
        A.a[kt][3] = pk_h2(p3.x, p3.y);
    }
}

__global__ void __launch_bounds__(TPB, 1)
nn_mma_kernel(const float* __restrict__ x,
              const float* __restrict__ Wn_g,
              const float* __restrict__ bn_g,
              const float* __restrict__ Ws_g,
              const float* __restrict__ bs_g,
              float* __restrict__ out)
{
    extern __shared__ unsigned char sm[];
    const uint32_t smb = smem_to_u32(sm);
    const int tid  = threadIdx.x;
    const int wid  = tid >> 5;
    const int lane = tid & 31;
    const int qt   = lane & 3;
    const int grp  = lane >> 2;

    // ---- stage 13 weight matrices as fp16, [n][k] row-major, SW128 ----
    for (int idx = tid; idx < 13 * 4096; idx += TPB) {
        int mat = idx >> 12, e = idx & 4095;
        float v = (mat < 7) ? Wn_g[mat * 4096 + e] : Ws_g[(mat - 7) * 4096 + e];
        int n = e >> 6, k = e & 63;
        uint32_t sw = SMEM_SWIZZLE_128B((uint32_t)(n * 128 + k * 2));
        *reinterpret_cast<__half*>(sm + OFF_W + mat * 8192 + sw) = __float2half_rn(v);
    }
    // fp32 biases (used by the LAST layer's exact epilogue)
    for (int i = tid; i < 448; i += TPB)
        reinterpret_cast<float*>(sm + OFF_BN)[i] = bn_g[i];
    for (int i = tid; i < 384; i += TPB)
        reinterpret_cast<float*>(sm + OFF_BS)[i] = bs_g[i];
    // half2-packed biases indexed [layer][nt*4+qt] (layers 1..6 epilogues)
    for (int i = tid; i < 224; i += TPB) {
        int t = i >> 5, r = i & 31, nt = r >> 2, q = r & 3;
        reinterpret_cast<__half2*>(sm + OFF_BNH)[i] =
            __floats2half2_rn(bn_g[t * 64 + nt * 8 + q * 2],
                              bn_g[t * 64 + nt * 8 + q * 2 + 1]);
    }
    for (int i = tid; i < 192; i += TPB) {
        int t = i >> 5, r = i & 31, nt = r >> 2, q = r & 3;
        reinterpret_cast<__half2*>(sm + OFF_BSH)[i] =
            __floats2half2_rn(bs_g[t * 64 + nt * 8 + q * 2],
                              bs_g[t * 64 + nt * 8 + q * 2 + 1]);
    }
    __syncthreads();

    // per-thread ldmatrix.x4 swizzled offsets (k halves 0-31 / 32-63)
    const int r8 = lane & 7, b4 = lane >> 3;
    const uint32_t soff0 = (uint32_t)(r8 * 128 + ((b4 * 16)      ^ (r8 * 16)));
    const uint32_t soff1 = (uint32_t)(r8 * 128 + ((b4 * 16 + 64) ^ (r8 * 16)));

    const float*   bn32 = reinterpret_cast<const float*>(sm + OFF_BN);
    const float*   bs32 = reinterpret_cast<const float*>(sm + OFF_BS);
    const __half2* bnh  = reinterpret_cast<const __half2*>(sm + OFF_BNH);
    const __half2* bsh  = reinterpret_cast<const __half2*>(sm + OFF_BSH);
    const uint32_t w0 = smb + OFF_W;

    // pinned zero quad for chain-start MMAs
    float z[4];
#pragma unroll
    for (int i = 0; i < 4; ++i)
        asm("mov.f32 %0, 0f00000000;" : "=f"(z[i]));

    // warps independent: global warp-strided loop over 32-row macro-groups
    const int gw = blockIdx.x * (TPB / 32) + wid;

    for (int g = gw; g < NMAC; g += WSTEP) {
        const size_t r00 = (size_t)g * 32 + grp;       // group0 rows
        const size_t r01 = r00 + 8;
        const size_t r10 = r00 + 16;                   // group1 rows
        const size_t r11 = r00 + 24;

        // 3 slots per group: h_t lives in S[t % 3] (S0 starts as h0 = x)
        Frag S0g0, S1g0, S2g0, S0g1, S1g1, S2g1;
        load_x(x + r00 * 64, x + r01 * 64, S0g0, qt);
        load_x(x + r10 * 64, x + r11 * 64, S0g1, qt);

        float* o00 = out + r00 * 64;
        float* o01 = out + r01 * 64;
        float* o10 = out + r10 * 64;
        float* o11 = out + r11 * 64;

        // layer t: Ap = S[(t-1)%3], As = S[(t-2)%3], An = S[t%3] (dead h_{t-3})
        layer_step<false, false>(S0g0, S0g0, S1g0, S0g1, S0g1, S1g1,
                                 w0 + 0 * 8192, 0, bnh + 0 * 32, bsh, bn32, bs32, z,
                                 soff0, soff1, qt, o00, o01, o10, o11);          // h1->S1
        layer_step<true,  false>(S1g0, S0g0, S2g0, S1g1, S0g1, S2g1,
                                 w0 + 1 * 8192, w0 + 7 * 8192,
                                 bnh + 1 * 32, bsh + 0 * 32, bn32, bs32, z,
                                 soff0, soff1, qt, o00, o01, o10, o11);          // h2->S2
        layer_step<true,  false>(S2g0, S1g0, S0g0, S2g1, S1g1, S0g1,
                                 w0 + 2 * 8192, w0 + 8 * 8192,
                                 bnh + 2 * 32, bsh + 1 * 32, bn32, bs32, z,
                                 soff0, soff1, qt, o00, o01, o10, o11);          // h3->S0
        layer_step<true,  false>(S0g0, S2g0, S1g0, S0g1, S2g1, S1g1,
                                 w0 + 3 * 8192, w0 + 9 * 8192,
                                 bnh + 3 * 32, bsh + 2 * 32, bn32, bs32, z,
                                 soff0, soff1, qt, o00, o01, o10, o11);          // h4->S1
        layer_step<true,  false>(S1g0, S0g0, S2g0, S1g1, S0g1, S2g1,
                                 w0 + 4 * 8192, w0 + 10 * 8192,
                                 bnh + 4 * 32, bsh + 3 * 32, bn32, bs32, z,
                                 soff0, soff1, qt, o00, o01, o10, o11);          // h5->S2
        layer_step<true,  false>(S2g0, S1g0, S0g0, S2g1, S1g1, S0g1,
                                 w0 + 5 * 8192, w0 + 11 * 8192,
                                 bnh + 5 * 32, bsh + 4 * 32, bn32, bs32, z,
                                 soff0, soff1, qt, o00, o01, o10, o11);          // h6->S0
        layer_step<true,  true >(S0g0, S2g0, S1g0, S0g1, S2g1, S1g1,
                                 w0 + 6 * 8192, w0 + 12 * 8192,
                                 bnh + 6 * 32, bsh + 5 * 32,
                                 bn32 + 6 * 64, bs32 + 5 * 64, z,
                                 soff0, soff1, qt, o00, o01, o10, o11);          // h7->out
    }
}

extern "C" void kernel_launch(void* const* d_in, const int* in_sizes, int n_in,
                              void* d_out, int out_size)
{
    const float* x  = (const float*)d_in[0];
    const float* Wn = (const float*)d_in[1];
    const float* bn = (const float*)d_in[2];
    const float* Ws = (const float*)d_in[3];
    const float* bs = (const float*)d_in[4];
    float* out = (float*)d_out;

    cudaFuncSetAttribute(nn_mma_kernel,
                         cudaFuncAttributeMaxDynamicSharedMemorySize, SMEM_TOTAL);
    nn_mma_kernel<<<GRID, TPB, SMEM_TOTAL>>>(x, Wn, bn, Ws, bs, out);
}